// round 2
// baseline (speedup 1.0000x reference)
#include <cuda_runtime.h>

// Problem geometry (fixed by the reference)
#define WIDTH   1000
#define HEIGHT  1000
#define PS      5
#define NT      10
#define PPR     (WIDTH / PS)          // 200 patches per patch-row
#define NPIX    (WIDTH * HEIGHT)      // 1,000,000

// Tiling: each block owns a 5-row x 250-col strip = 50 patches = 1250 pixels.
constexpr int PATCHES_PER_BLOCK = 50;
constexpr int COLS_PER_BLOCK    = PATCHES_PER_BLOCK * PS;   // 250
constexpr int SEGS_PER_ROWSTRIP = WIDTH / COLS_PER_BLOCK;   // 4
constexpr int PIX_PER_BLOCK     = COLS_PER_BLOCK * PS;      // 1250
constexpr int THREADS           = 256;
constexpr int COEF_PER_PATCH    = 3 * NT * 2;               // 60 floats

__global__ __launch_bounds__(THREADS)
void ts_approx_kernel(const float* __restrict__ pix,     // [NPIX, 2]
                      const float* __restrict__ coef,    // [NPATCH, 3, NT, 2]
                      const float* __restrict__ bias,    // [NPATCH, 3]
                      float* __restrict__ out)           // [3, NPIX]
{
    __shared__ float s_coef[PATCHES_PER_BLOCK * COEF_PER_PATCH]; // 12000 B
    __shared__ float s_bias[PATCHES_PER_BLOCK * 3];

    const int b      = blockIdx.x;
    const int pr     = b / SEGS_PER_ROWSTRIP;     // patch-row 0..199
    const int seg    = b % SEGS_PER_ROWSTRIP;     // 0..3
    const int patch0 = pr * PPR + seg * PATCHES_PER_BLOCK;

    // Stage this block's 50 patches of coefficients: 3000 floats, CONTIGUOUS
    // in gmem (patch_idx is row-major) -> fully coalesced float4 loads.
    {
        const float4* gc = reinterpret_cast<const float4*>(coef + (size_t)patch0 * COEF_PER_PATCH);
        float4* sc = reinterpret_cast<float4*>(s_coef);
        #pragma unroll
        for (int i = threadIdx.x; i < PATCHES_PER_BLOCK * (COEF_PER_PATCH / 4); i += THREADS)
            sc[i] = gc[i];
        for (int i = threadIdx.x; i < PATCHES_PER_BLOCK * 3; i += THREADS)
            s_bias[i] = bias[patch0 * 3 + i];
    }
    __syncthreads();

    const int col0 = seg * COLS_PER_BLOCK;
    const int row0 = pr * PS;
    const float2* __restrict__ pix2 = reinterpret_cast<const float2*>(pix);

    for (int i = threadIdx.x; i < PIX_PER_BLOCK; i += THREADS) {
        const int r = i / COLS_PER_BLOCK;             // 0..4 (image row within strip)
        const int c = i - r * COLS_PER_BLOCK;         // 0..249
        const int n = (row0 + r) * WIDTH + col0 + c;  // global pixel index

        const float2 p = pix2[n];
        const float x = p.x, y = p.y;

        const int pl = c / PS;                        // local patch 0..49
        // Lane addresses stride 60 floats (240B) across the warp's ~7 distinct
        // patches -> distinct banks -> conflict-free LDS.128.
        const float4* cf = reinterpret_cast<const float4*>(s_coef) + pl * 15;

        #pragma unroll
        for (int ch = 0; ch < 3; ch++) {
            // Layout per channel: 5 float4 = {a_t, b_t, a_{t+1}, b_{t+1}} for t=0,2,4,6,8
            const float4 q0 = cf[ch * 5 + 0];
            const float4 q1 = cf[ch * 5 + 1];
            const float4 q2 = cf[ch * 5 + 2];
            const float4 q3 = cf[ch * 5 + 3];
            const float4 q4 = cf[ch * 5 + 4];

            // Separable Horner: sum_t a_t x^t  and  sum_t b_t y^t
            float hx = q4.z;                 // a9
            float hy = q4.w;                 // b9
            hx = fmaf(hx, x, q4.x);  hy = fmaf(hy, y, q4.y);   // a8 / b8
            hx = fmaf(hx, x, q3.z);  hy = fmaf(hy, y, q3.w);   // a7 / b7
            hx = fmaf(hx, x, q3.x);  hy = fmaf(hy, y, q3.y);   // a6 / b6
            hx = fmaf(hx, x, q2.z);  hy = fmaf(hy, y, q2.w);   // a5 / b5
            hx = fmaf(hx, x, q2.x);  hy = fmaf(hy, y, q2.y);   // a4 / b4
            hx = fmaf(hx, x, q1.z);  hy = fmaf(hy, y, q1.w);   // a3 / b3
            hx = fmaf(hx, x, q1.x);  hy = fmaf(hy, y, q1.y);   // a2 / b2
            hx = fmaf(hx, x, q0.z);  hy = fmaf(hy, y, q0.w);   // a1 / b1
            hx = fmaf(hx, x, q0.x);  hy = fmaf(hy, y, q0.y);   // a0 / b0

            out[(size_t)ch * NPIX + n] = hx + hy + s_bias[pl * 3 + ch];
        }
    }
}

extern "C" void kernel_launch(void* const* d_in, const int* in_sizes, int n_in,
                              void* d_out, int out_size)
{
    const float* pix  = (const float*)d_in[0];   // [1e6, 2]
    const float* coef = (const float*)d_in[1];   // [40000, 3, 10, 2]
    const float* bias = (const float*)d_in[2];   // [40000, 3]
    float* out        = (float*)d_out;           // [3, 1e6]

    const int nblocks = (HEIGHT / PS) * SEGS_PER_ROWSTRIP;   // 200 * 4 = 800
    ts_approx_kernel<<<nblocks, THREADS>>>(pix, coef, bias, out);
}

// round 3
// speedup vs baseline: 1.3908x; 1.3908x over previous
#include <cuda_runtime.h>

// Problem geometry (fixed by the reference)
#define WIDTH   1000
#define HEIGHT  1000
#define PS      5
#define NT      10
#define PPR     (WIDTH / PS)          // 200 patches per patch-row
#define NPIX    (WIDTH * HEIGHT)      // 1,000,000

constexpr int PATCHES_PER_BLOCK = 50;
constexpr int COLS_PER_BLOCK    = PATCHES_PER_BLOCK * PS;   // 250
constexpr int SEGS_PER_ROWSTRIP = WIDTH / COLS_PER_BLOCK;   // 4
constexpr int THREADS           = 256;
constexpr int COEF_PER_PATCH    = 3 * NT * 2;               // 60 floats = 240 B

using ull = unsigned long long;

// Packed dual-FMA: lo = a.lo*b.lo + c.lo ; hi = a.hi*b.hi + c.hi
// (Blackwell f32x2 pipe; ptxas never emits this from plain C++.)
__device__ __forceinline__ ull fma2(ull a, ull b, ull c) {
    ull d;
    asm("fma.rn.f32x2 %0, %1, %2, %3;" : "=l"(d) : "l"(a), "l"(b), "l"(c));
    return d;
}

__device__ __forceinline__ void unpack2(ull h, float& lo, float& hi) {
    asm("mov.b64 {%0, %1}, %2;" : "=f"(lo), "=f"(hi) : "l"(h));
}

__global__ __launch_bounds__(THREADS)
void ts_approx_kernel(const float* __restrict__ pix,     // [NPIX, 2]
                      const float* __restrict__ coef,    // [NPATCH, 3, NT, 2]
                      const float* __restrict__ bias,    // [NPATCH, 3]
                      float* __restrict__ out)           // [3, NPIX]
{
    __shared__ float s_coef[PATCHES_PER_BLOCK * COEF_PER_PATCH]; // 12000 B
    __shared__ float s_bias[PATCHES_PER_BLOCK * 3];

    const int b      = blockIdx.x;
    const int pr     = b / SEGS_PER_ROWSTRIP;     // patch-row 0..199
    const int seg    = b % SEGS_PER_ROWSTRIP;     // 0..3
    const int patch0 = pr * PPR + seg * PATCHES_PER_BLOCK;

    // Stage 50 patches of coefficients (contiguous in gmem) via coalesced float4.
    {
        const float4* gc = reinterpret_cast<const float4*>(coef + (size_t)patch0 * COEF_PER_PATCH);
        float4* sc = reinterpret_cast<float4*>(s_coef);
        #pragma unroll
        for (int i = threadIdx.x; i < PATCHES_PER_BLOCK * (COEF_PER_PATCH / 4); i += THREADS)
            sc[i] = gc[i];
        for (int i = threadIdx.x; i < PATCHES_PER_BLOCK * 3; i += THREADS)
            s_bias[i] = bias[patch0 * 3 + i];
    }
    __syncthreads();

    // One thread per image COLUMN of the strip; it owns all 5 rows -> all 5
    // pixels share ONE patch -> coefficients live in registers, amortized 5x.
    const int c = threadIdx.x;
    if (c >= COLS_PER_BLOCK) return;

    const int col  = seg * COLS_PER_BLOCK + c;
    const int row0 = pr * PS;
    const int pl   = c / PS;                      // local patch 0..49
    const int n0   = row0 * WIDTH + col;

    // Load the 5 packed (x,y) pairs — coalesced 8B loads per row.
    const ull* __restrict__ pixq = reinterpret_cast<const ull*>(pix);
    ull xy[PS];
    #pragma unroll
    for (int r = 0; r < PS; r++)
        xy[r] = pixq[n0 + r * WIDTH];

    #pragma unroll
    for (int ch = 0; ch < 3; ch++) {
        // 10 coefficient pairs (a_t,b_t) for this channel: 5 x 16B smem loads.
        // Lane stride across warp = 240B -> 7 distinct banks-groups, conflict-free.
        const ulonglong2* cfc =
            reinterpret_cast<const ulonglong2*>(s_coef) + pl * 15 + ch * 5;
        const ulonglong2 u0 = cfc[0];   // (c0, c1)
        const ulonglong2 u1 = cfc[1];   // (c2, c3)
        const ulonglong2 u2 = cfc[2];   // (c4, c5)
        const ulonglong2 u3 = cfc[3];   // (c6, c7)
        const ulonglong2 u4 = cfc[4];   // (c8, c9)
        const float bch = s_bias[pl * 3 + ch];

        // 5 independent packed Horner chains (one per row) -> good ILP.
        #pragma unroll
        for (int r = 0; r < PS; r++) {
            ull h = u4.y;                  // (a9, b9)
            h = fma2(h, xy[r], u4.x);      // + (a8, b8)
            h = fma2(h, xy[r], u3.y);
            h = fma2(h, xy[r], u3.x);
            h = fma2(h, xy[r], u2.y);
            h = fma2(h, xy[r], u2.x);
            h = fma2(h, xy[r], u1.y);
            h = fma2(h, xy[r], u1.x);
            h = fma2(h, xy[r], u0.y);
            h = fma2(h, xy[r], u0.x);      // + (a0, b0)
            float hx, hy;
            unpack2(h, hx, hy);
            out[(size_t)ch * NPIX + n0 + r * WIDTH] = hx + hy + bch;
        }
    }
}

extern "C" void kernel_launch(void* const* d_in, const int* in_sizes, int n_in,
                              void* d_out, int out_size)
{
    const float* pix  = (const float*)d_in[0];   // [1e6, 2]
    const float* coef = (const float*)d_in[1];   // [40000, 3, 10, 2]
    const float* bias = (const float*)d_in[2];   // [40000, 3]
    float* out        = (float*)d_out;           // [3, 1e6]

    const int nblocks = (HEIGHT / PS) * SEGS_PER_ROWSTRIP;   // 200 * 4 = 800
    ts_approx_kernel<<<nblocks, THREADS>>>(pix, coef, bias, out);
}

// round 4
// speedup vs baseline: 1.6741x; 1.2037x over previous
#include <cuda_runtime.h>

// Problem geometry (fixed by the reference)
#define WIDTH   1000
#define HEIGHT  1000
#define PS      5
#define NT      10
#define PPR     (WIDTH / PS)          // 200 patches per patch-row
#define NPIX    (WIDTH * HEIGHT)      // 1,000,000

constexpr int PATCHES_PER_BLOCK = 25;
constexpr int COLS_PER_BLOCK    = PATCHES_PER_BLOCK * PS;   // 125
constexpr int SEGS_PER_ROWSTRIP = WIDTH / COLS_PER_BLOCK;   // 8
constexpr int THREADS           = 128;
constexpr int COEF_PER_PATCH    = 3 * NT * 2;               // 60 floats = 240 B
constexpr int COEF_VEC16        = PATCHES_PER_BLOCK * COEF_PER_PATCH / 4; // 375 x 16B

using ull = unsigned long long;

// Packed dual-FMA on the f32x2 pipe (ptxas never auto-fuses this).
__device__ __forceinline__ ull fma2(ull a, ull b, ull c) {
    ull d;
    asm("fma.rn.f32x2 %0, %1, %2, %3;" : "=l"(d) : "l"(a), "l"(b), "l"(c));
    return d;
}
__device__ __forceinline__ void unpack2(ull h, float& lo, float& hi) {
    asm("mov.b64 {%0, %1}, %2;" : "=f"(lo), "=f"(hi) : "l"(h));
}
__device__ __forceinline__ void cp_async16(void* smem_dst, const void* gmem_src) {
    unsigned saddr = (unsigned)__cvta_generic_to_shared(smem_dst);
    asm volatile("cp.async.cg.shared.global [%0], [%1], 16;" :: "r"(saddr), "l"(gmem_src));
}

__global__ __launch_bounds__(THREADS)
void ts_approx_kernel(const float* __restrict__ pix,     // [NPIX, 2]
                      const float* __restrict__ coef,    // [NPATCH, 3, NT, 2]
                      const float* __restrict__ bias,    // [NPATCH, 3]
                      float* __restrict__ out)           // [3, NPIX]
{
    __shared__ float s_coef[PATCHES_PER_BLOCK * COEF_PER_PATCH]; // 6000 B
    __shared__ float s_bias[PATCHES_PER_BLOCK * 3];              // 300 B

    const int b      = blockIdx.x;
    const int pr     = b / SEGS_PER_ROWSTRIP;     // patch-row 0..199
    const int seg    = b % SEGS_PER_ROWSTRIP;     // 0..7
    const int patch0 = pr * PPR + seg * PATCHES_PER_BLOCK;

    const int c    = threadIdx.x;                 // column within strip (0..124 active)
    const int col  = seg * COLS_PER_BLOCK + c;
    const int row0 = pr * PS;
    const int n0   = row0 * WIDTH + col;

    // ── Issue the 5 pixel loads FIRST so their DRAM latency overlaps staging.
    const ull* __restrict__ pixq = reinterpret_cast<const ull*>(pix);
    ull xy[PS];
    if (c < COLS_PER_BLOCK) {
        #pragma unroll
        for (int r = 0; r < PS; r++)
            xy[r] = pixq[n0 + r * WIDTH];
    }

    // ── Stage coefficients via cp.async (no reg roundtrip, overlaps with above).
    {
        const float4* gc = reinterpret_cast<const float4*>(coef + (size_t)patch0 * COEF_PER_PATCH);
        float4* sc = reinterpret_cast<float4*>(s_coef);
        #pragma unroll
        for (int i = threadIdx.x; i < COEF_VEC16; i += THREADS)
            cp_async16(sc + i, gc + i);
        if (threadIdx.x < PATCHES_PER_BLOCK * 3)
            s_bias[threadIdx.x] = bias[patch0 * 3 + threadIdx.x];
        asm volatile("cp.async.commit_group;\n cp.async.wait_group 0;" ::: "memory");
    }
    __syncthreads();

    if (c >= COLS_PER_BLOCK) return;

    const int pl = c / PS;                        // local patch 0..24

    #pragma unroll
    for (int ch = 0; ch < 3; ch++) {
        // 10 coefficient pairs (a_t,b_t): 5 x 16B smem loads, lane stride 240B
        // across ~7 distinct patches per warp -> conflict-free.
        const ulonglong2* cfc =
            reinterpret_cast<const ulonglong2*>(s_coef) + pl * 15 + ch * 5;
        const ulonglong2 u0 = cfc[0];   // (c0, c1)
        const ulonglong2 u1 = cfc[1];   // (c2, c3)
        const ulonglong2 u2 = cfc[2];   // (c4, c5)
        const ulonglong2 u3 = cfc[3];   // (c6, c7)
        const ulonglong2 u4 = cfc[4];   // (c8, c9)
        const float bch = s_bias[pl * 3 + ch];

        // 5 independent packed Horner chains (one per row) -> ILP 5.
        #pragma unroll
        for (int r = 0; r < PS; r++) {
            ull h = u4.y;                  // (a9, b9)
            h = fma2(h, xy[r], u4.x);
            h = fma2(h, xy[r], u3.y);
            h = fma2(h, xy[r], u3.x);
            h = fma2(h, xy[r], u2.y);
            h = fma2(h, xy[r], u2.x);
            h = fma2(h, xy[r], u1.y);
            h = fma2(h, xy[r], u1.x);
            h = fma2(h, xy[r], u0.y);
            h = fma2(h, xy[r], u0.x);      // + (a0, b0)
            float hx, hy;
            unpack2(h, hx, hy);
            out[(size_t)ch * NPIX + n0 + r * WIDTH] = hx + (hy + bch);
        }
    }
}

extern "C" void kernel_launch(void* const* d_in, const int* in_sizes, int n_in,
                              void* d_out, int out_size)
{
    const float* pix  = (const float*)d_in[0];   // [1e6, 2]
    const float* coef = (const float*)d_in[1];   // [40000, 3, 10, 2]
    const float* bias = (const float*)d_in[2];   // [40000, 3]
    float* out        = (float*)d_out;           // [3, 1e6]

    const int nblocks = (HEIGHT / PS) * SEGS_PER_ROWSTRIP;   // 200 * 8 = 1600
    ts_approx_kernel<<<nblocks, THREADS>>>(pix, coef, bias, out);
}